// round 13
// baseline (speedup 1.0000x reference)
#include <cuda_runtime.h>
#include <cuda_fp16.h>
#include <math.h>
#include <stdint.h>

// Problem constants
#define B_    512
#define N_    64
#define H_    256
#define BN_   32768          // B_*N_
#define KX    768            // X = [P_in(256) | P_out(256) | h(256)]
#define NG    1024           // G columns: [r-sum | i-sum | i_n | h_n]

// ---------------- device scratch (static, allocation-free) ----------------
__device__ __half g_X[(size_t)BN_ * KX];        // fp16 activations [32768,768]
__device__ __half g_G[(size_t)BN_ * NG];        // fp16 [32768,1024]
__device__ __half g_Wpack[NG * KX];             // packed weight [1024,768] fp16
__device__ __half g_wih16[768 * 512];           // w_ih fp16
__device__ __half g_WinT[256 * 256];            // W_in^T fp16
__device__ __half g_WoutT[256 * 256];           // W_out^T fp16
__device__ float  g_uin[NG];                    // w_ih1 @ b_in
__device__ float  g_uout[NG];                   // w_ih2 @ b_out
__device__ float  g_v[NG];                      // folded constant bias
__device__ float  g_S[BN_ * 2];                 // rowsums [s_in, s_out]
__device__ float  g_zero[256];

// ---------------- K0: pack weights + fold biases (merged) ----------
__global__ void build_pack_fold(
    const float* __restrict__ w_ih, const float* __restrict__ w_hh,
    const float* __restrict__ W_in, const float* __restrict__ W_out,
    const float* __restrict__ b_ih, const float* __restrict__ b_hh,
    const float* __restrict__ b_in, const float* __restrict__ b_out,
    const float* __restrict__ b_iah, const float* __restrict__ b_oah)
{
    const int stride = gridDim.x * blockDim.x;
    const int idx = blockIdx.x * blockDim.x + threadIdx.x;

    for (int i = idx; i < 768 * 512; i += stride)
        g_wih16[i] = __float2half_rn(w_ih[i]);
    for (int i = idx; i < 256 * 256; i += stride) {
        int k = i >> 8, j = i & 255;
        g_WinT[i]  = __float2half_rn(W_in[j * 256 + k]);
        g_WoutT[i] = __float2half_rn(W_out[j * 256 + k]);
    }
    // Wpack h-columns (512..768)
    for (int i = idx; i < NG * 256; i += stride) {
        int n = i >> 8, k = i & 255;
        float v;
        if (n < 512)      v = w_hh[n * 256 + k];
        else if (n < 768) v = 0.f;
        else              v = w_hh[(n - 256) * 256 + k];
        g_Wpack[(size_t)n * KX + 512 + k] = __float2half_rn(v);
    }
    for (int i = idx; i < 256; i += stride) g_zero[i] = 0.f;

    // fold biases: blocks 0..127 handle 8 n's each (warp per n)
    if (blockIdx.x < 128) {
        const int n = blockIdx.x * 8 + (threadIdx.x >> 5);
        const int lane = threadIdx.x & 31;
        if (n < 768) {
            const float* wr = w_ih + (size_t)n * 512;
            float d1 = 0.f, d2 = 0.f, d3 = 0.f, d4 = 0.f;
            #pragma unroll
            for (int j = lane; j < 256; j += 32) {
                float a = wr[j], c = wr[256 + j];
                d1 += a * b_in[j];
                d3 += a * b_iah[j];
                d2 += c * b_out[j];
                d4 += c * b_oah[j];
            }
            #pragma unroll
            for (int o = 16; o > 0; o >>= 1) {
                d1 += __shfl_xor_sync(0xffffffffu, d1, o);
                d2 += __shfl_xor_sync(0xffffffffu, d2, o);
                d3 += __shfl_xor_sync(0xffffffffu, d3, o);
                d4 += __shfl_xor_sync(0xffffffffu, d4, o);
            }
            if (lane == 0) {
                g_uin[n] = d1;
                g_uout[n] = d2;
                g_v[n] = d3 + d4 + b_ih[n] + (n < 512 ? b_hh[n] : 0.f);
            }
        } else if (lane == 0) {
            g_uin[n] = 0.f;
            g_uout[n] = 0.f;
            g_v[n] = b_hh[n - 256];
        }
    }
}

// ---------------- K1: gather + L2 normalize (warp per row) ----------
__global__ void __launch_bounds__(256) gather_norm(const int* __restrict__ inputs,
                                                   const float* __restrict__ emb)
{
    const int row = blockIdx.x * 8 + (threadIdx.x >> 5);
    const int lane = threadIdx.x & 31;
    const float4* e = (const float4*)(emb + (size_t)inputs[row] * H_) + lane * 2;
    float4 v0 = e[0], v1 = e[1];
    float ss = v0.x * v0.x + v0.y * v0.y + v0.z * v0.z + v0.w * v0.w
             + v1.x * v1.x + v1.y * v1.y + v1.z * v1.z + v1.w * v1.w;
    #pragma unroll
    for (int o = 16; o > 0; o >>= 1) ss += __shfl_xor_sync(0xffffffffu, ss, o);
    float sc = 1.f / (sqrtf(ss) + 1e-12f);
    __half2 h[4];
    h[0] = __floats2half2_rn(v0.x * sc, v0.y * sc);
    h[1] = __floats2half2_rn(v0.z * sc, v0.w * sc);
    h[2] = __floats2half2_rn(v1.x * sc, v1.y * sc);
    h[3] = __floats2half2_rn(v1.z * sc, v1.w * sc);
    *(uint4*)&g_X[(size_t)row * KX + 512 + lane * 8] = *(uint4*)h;
}

// ---------------- helpers ----------------
__device__ __forceinline__ void cp_async16(void* smem_dst, const void* gmem_src) {
    uint32_t sa = (uint32_t)__cvta_generic_to_shared(smem_dst);
    asm volatile("cp.async.cg.shared.global [%0], [%1], 16;\n" :: "r"(sa), "l"(gmem_src));
}
__device__ __forceinline__ void cp_commit() { asm volatile("cp.async.commit_group;\n"); }

__device__ __forceinline__ void ldm_x4(uint32_t& r0, uint32_t& r1, uint32_t& r2, uint32_t& r3,
                                       uint32_t addr) {
    asm volatile("ldmatrix.sync.aligned.m8n8.x4.shared.b16 {%0,%1,%2,%3}, [%4];"
                 : "=r"(r0), "=r"(r1), "=r"(r2), "=r"(r3) : "r"(addr));
}
__device__ __forceinline__ void ldm_x4_t(uint32_t& r0, uint32_t& r1, uint32_t& r2, uint32_t& r3,
                                         uint32_t addr) {
    asm volatile("ldmatrix.sync.aligned.m8n8.x4.trans.shared.b16 {%0,%1,%2,%3}, [%4];"
                 : "=r"(r0), "=r"(r1), "=r"(r2), "=r"(r3) : "r"(addr));
}
#define HMMA16816(ac, a0, a1, a2, a3, b0, b1)                                          \
    asm volatile(                                                                      \
        "mma.sync.aligned.m16n8k16.row.col.f32.f16.f16.f32 "                           \
        "{%0,%1,%2,%3}, {%4,%5,%6,%7}, {%8,%9}, {%0,%1,%2,%3};\n"                      \
        : "+f"((ac)[0]), "+f"((ac)[1]), "+f"((ac)[2]), "+f"((ac)[3])                   \
        : "r"(a0), "r"(a1), "r"(a2), "r"(a3), "r"(b0), "r"(b1))

// ---------------- GEMM body: 4-stage BK=32 pipeline (proven fastest) -------
#define ST_STRIDE 20                     // u32 per smem row (80 B, 16B aligned)
#define ST_TILE_U32 (128 * ST_STRIDE)    // 2560 u32 per tile
#define ST_STAGE_U32 (2 * ST_TILE_U32)   // 5120 u32 per stage
#define GM_SMEM (4 * ST_STAGE_U32 * 4)   // 81920 bytes

__device__ __forceinline__ void gemm_body(
    const __half* __restrict__ gA, int lda,
    const __half* __restrict__ gB, int ldb,
    const float* __restrict__ biasB,
    __half* __restrict__ Cb, int ldc,
    int kb, int ke)
{
    extern __shared__ uint32_t sm[];
    const uint32_t smBase = (uint32_t)__cvta_generic_to_shared(sm);

    const int tid = threadIdx.x;
    const int lane = tid & 31;
    const int g = lane >> 2;
    const int t = lane & 3;
    const int warpId = tid >> 5;
    const int wm = (warpId >> 2) * 64;
    const int wn = (warpId & 3) * 32;
    const int T = (ke - kb) >> 5;

    const int ldRow0 = tid >> 2;
    const int ldCol0 = (tid & 3);
    const int ldRow1 = (tid + 256) >> 2;
    const int ldCol1 = (tid + 256) & 3;

    const uint32_t aOff = (uint32_t)(((wm + (lane & 15)) * ST_STRIDE + (lane >> 4) * 4) * 4);
    const uint32_t bOff = (uint32_t)(((wn + (lane >> 4) * 8 + (lane & 7)) * ST_STRIDE
                                      + ((lane >> 3) & 1) * 4) * 4);

    float acc[4][4][4];
    #pragma unroll
    for (int i = 0; i < 4; i++)
        #pragma unroll
        for (int j = 0; j < 4; j++)
            #pragma unroll
            for (int c = 0; c < 4; c++) acc[i][j][c] = 0.f;

    auto load_stage = [&](int slot, int k0) {
        uint32_t* As = sm + slot * ST_STAGE_U32;
        uint32_t* Bs = As + ST_TILE_U32;
        cp_async16(As + ldRow0 * ST_STRIDE + ldCol0 * 4,
                   gA + (size_t)ldRow0 * lda + k0 + ldCol0 * 8);
        cp_async16(As + ldRow1 * ST_STRIDE + ldCol1 * 4,
                   gA + (size_t)ldRow1 * lda + k0 + ldCol1 * 8);
        cp_async16(Bs + ldRow0 * ST_STRIDE + ldCol0 * 4,
                   gB + (size_t)ldRow0 * ldb + k0 + ldCol0 * 8);
        cp_async16(Bs + ldRow1 * ST_STRIDE + ldCol1 * 4,
                   gB + (size_t)ldRow1 * ldb + k0 + ldCol1 * 8);
        cp_commit();
    };

    load_stage(0, kb);
    load_stage(1, kb + 32);
    load_stage(2, kb + 64);

    for (int kt = 0; kt < T; kt++) {
        if (kt <= T - 3)      asm volatile("cp.async.wait_group 2;\n" ::: "memory");
        else if (kt == T - 2) asm volatile("cp.async.wait_group 1;\n" ::: "memory");
        else                  asm volatile("cp.async.wait_group 0;\n" ::: "memory");
        __syncthreads();

        if (kt + 3 < T)
            load_stage((kt + 3) & 3, kb + (kt + 3) * 32);

        const uint32_t As_b = smBase + (uint32_t)((kt & 3) * ST_STAGE_U32 * 4);
        const uint32_t Bs_b = As_b + ST_TILE_U32 * 4;

        #pragma unroll
        for (int kk = 0; kk < 2; kk++) {
            uint32_t a[4][4];
            #pragma unroll
            for (int mt = 0; mt < 4; mt++)
                ldm_x4(a[mt][0], a[mt][1], a[mt][2], a[mt][3],
                       As_b + aOff + mt * (16 * ST_STRIDE * 4) + kk * 32);
            uint32_t b[4][2];
            ldm_x4(b[0][0], b[0][1], b[1][0], b[1][1], Bs_b + bOff + kk * 32);
            ldm_x4(b[2][0], b[2][1], b[3][0], b[3][1],
                   Bs_b + bOff + 2 * (8 * ST_STRIDE * 4) + kk * 32);

            #pragma unroll
            for (int mt = 0; mt < 4; mt++)
                #pragma unroll
                for (int nt = 0; nt < 4; nt++)
                    HMMA16816(acc[mt][nt], a[mt][0], a[mt][1], a[mt][2], a[mt][3],
                              b[nt][0], b[nt][1]);
        }
    }

    #pragma unroll
    for (int nt = 0; nt < 4; nt++) {
        const int col = wn + nt * 8 + t * 2;
        const float b0 = biasB[col], b1 = biasB[col + 1];
        #pragma unroll
        for (int mt = 0; mt < 4; mt++) {
            const int row = wm + mt * 16 + g;
            *(__half2*)(Cb + (size_t)row * ldc + col) =
                __floats2half2_rn(acc[mt][nt][0] + b0, acc[mt][nt][1] + b1);
            *(__half2*)(Cb + (size_t)(row + 8) * ldc + col) =
                __floats2half2_rn(acc[mt][nt][2] + b0, acc[mt][nt][3] + b1);
        }
    }
}

// ---------------- K2: merged Wpack M-GEMMs (one launch) ----------
__global__ void __launch_bounds__(256, 2) wpack_gemm()
{
    const int m0 = blockIdx.x * 128;
    const int sel = blockIdx.y >> 1;
    const int n0 = (blockIdx.y & 1) * 128;
    const __half* gA = g_wih16 + (size_t)m0 * 512 + sel * 256;
    const __half* gB = (sel ? g_WoutT : g_WinT) + (size_t)n0 * 256;
    __half* Cb = g_Wpack + (size_t)m0 * KX + sel * 256 + n0;
    gemm_body(gA, 512, gB, 256, g_zero, Cb, KX, 0, 256);
}

// ---------------- K4: GEMM2 (grouped K) -> g_G ----------------
__global__ void __launch_bounds__(256, 2) gemm2()
{
    const int m0 = blockIdx.x * 128;
    const int n0 = blockIdx.y * 128;
    int kb, ke;
    if (n0 >= 768)      { kb = 512; ke = 768; }
    else if (n0 >= 512) { kb = 0;   ke = 512; }
    else                { kb = 0;   ke = 768; }
    gemm_body(g_X + (size_t)m0 * KX, KX,
              g_Wpack + (size_t)n0 * KX, KX,
              g_v + n0,
              g_G + (size_t)m0 * NG + n0, NG, kb, ke);
}

// ---------------- K3: adjacency, one CTA per batch; h loaded once ----------
// P_half = A_half @ h; both halves computed from one resident h tile.
#define SA2_STRIDE 68     // u32 per A row (128 halves + 4 pad), 272 B (16B-mult)
#define SH2_STRIDE 132    // u32 per h row (256 halves + 4 pad)
__global__ void __launch_bounds__(256) adjacency_mma(const float* __restrict__ Aadj)
{
    __shared__ __align__(16) uint32_t shA[64 * SA2_STRIDE];   // 17408 B
    __shared__ __align__(16) uint32_t shH[64 * SH2_STRIDE];   // 33792 B
    const int b = blockIdx.x;
    const int tid = threadIdx.x;
    const int lane = tid & 31;
    const int wid = tid >> 5;
    const int mw = wid >> 2;           // 0..1 (32 rows)
    const int nw = wid & 3;            // 0..3 (64 cols)
    const int g = lane >> 2;
    const int t = lane & 3;
    const float* Ab = Aadj + (size_t)b * (64 * 128);
    const int r0 = b * 64;

    const uint32_t shA_b = (uint32_t)__cvta_generic_to_shared(shA);
    const uint32_t shH_b = (uint32_t)__cvta_generic_to_shared(shH);

    // load full A (64x128 fp32 -> fp16), both halves
    for (int i = tid; i < 64 * 64; i += 256) {
        int n = i >> 6, m2 = (i & 63) * 2;
        float2 v = *(const float2*)&Ab[n * 128 + m2];
        *(__half2*)&shA[n * SA2_STRIDE + m2 / 2] = __floats2half2_rn(v.x, v.y);
    }
    // load h (64x256 fp16), once
    for (int i = tid; i < 64 * 32; i += 256) {
        int m = i >> 5, c8 = (i & 31) * 8;
        uint4 v = *(const uint4*)&g_X[(size_t)(r0 + m) * KX + 512 + c8];
        *(uint4*)&shH[m * SH2_STRIDE + c8 / 2] = v;
    }
    // rowsums, both halves (threads 0..127)
    if (tid < 128) {
        const int half = tid >> 6, n = tid & 63;
        const float* ar = Ab + n * 128 + half * 64;
        float s = 0.f;
        #pragma unroll 8
        for (int m = 0; m < 64; m++) s += ar[m];
        g_S[(size_t)(r0 + n) * 2 + half] = s;
    }
    __syncthreads();

    const uint32_t aOffE = (uint32_t)(((mw * 32 + (lane & 15)) * SA2_STRIDE
                                       + (lane >> 4) * 4) * 4);
    const uint32_t hOffE = (uint32_t)(((lane & 15) * SH2_STRIDE + nw * 32
                                       + (lane >> 4) * 4) * 4);

    #pragma unroll
    for (int half = 0; half < 2; half++) {
        float acc[2][8][4];
        #pragma unroll
        for (int i = 0; i < 2; i++)
            #pragma unroll
            for (int j = 0; j < 8; j++)
                #pragma unroll
                for (int c = 0; c < 4; c++) acc[i][j][c] = 0.f;

        #pragma unroll
        for (int kk = 0; kk < 4; kk++) {
            uint32_t a[2][4];
            #pragma unroll
            for (int mt = 0; mt < 2; mt++)
                ldm_x4(a[mt][0], a[mt][1], a[mt][2], a[mt][3],
                       shA_b + aOffE + mt * (16 * SA2_STRIDE * 4)
                       + half * 128 + kk * 32);
            uint32_t bb[8][2];
            #pragma unroll
            for (int q = 0; q < 4; q++)
                ldm_x4_t(bb[q * 2][0], bb[q * 2][1], bb[q * 2 + 1][0], bb[q * 2 + 1][1],
                         shH_b + hOffE + kk * (16 * SH2_STRIDE * 4) + q * 32);
            #pragma unroll
            for (int mt = 0; mt < 2; mt++)
                #pragma unroll
                for (int nt = 0; nt < 8; nt++)
                    HMMA16816(acc[mt][nt], a[mt][0], a[mt][1], a[mt][2], a[mt][3],
                              bb[nt][0], bb[nt][1]);
        }

        #pragma unroll
        for (int nt = 0; nt < 8; nt++) {
            const int c = nw * 64 + nt * 8 + t * 2;
            #pragma unroll
            for (int mt = 0; mt < 2; mt++) {
                const int n = mw * 32 + mt * 16 + g;
                *(__half2*)&g_X[(size_t)(r0 + n) * KX + half * 256 + c] =
                    __floats2half2_rn(acc[mt][nt][0], acc[mt][nt][1]);
                *(__half2*)&g_X[(size_t)(r0 + n + 8) * KX + half * 256 + c] =
                    __floats2half2_rn(acc[mt][nt][2], acc[mt][nt][3]);
            }
        }
    }
}

// ---------------- K5: gates epilogue -> out ----------------
__global__ void __launch_bounds__(256) gates_kernel(float* __restrict__ out)
{
    int idx = blockIdx.x * blockDim.x + threadIdx.x;
    if (idx >= BN_ * 32) return;
    int r = idx >> 5;
    int c = (idx & 31) << 3;
    const __half* Gr = g_G + (size_t)r * NG;
    uint4 vr = *(const uint4*)&Gr[c];
    uint4 vi = *(const uint4*)&Gr[256 + c];
    uint4 vn = *(const uint4*)&Gr[512 + c];
    uint4 vh = *(const uint4*)&Gr[768 + c];
    uint4 vx = *(const uint4*)&g_X[(size_t)r * KX + 512 + c];
    const __half2* pr = (const __half2*)&vr;
    const __half2* pi = (const __half2*)&vi;
    const __half2* pn = (const __half2*)&vn;
    const __half2* ph = (const __half2*)&vh;
    const __half2* px = (const __half2*)&vx;

    float2 s2 = *(const float2*)&g_S[(size_t)r * 2];
    float uin[3][8], uout[3][8];
    #pragma unroll
    for (int g3 = 0; g3 < 3; g3++) {
        *(float4*)&uin[g3][0]  = *(const float4*)&g_uin[g3 * 256 + c];
        *(float4*)&uin[g3][4]  = *(const float4*)&g_uin[g3 * 256 + c + 4];
        *(float4*)&uout[g3][0] = *(const float4*)&g_uout[g3 * 256 + c];
        *(float4*)&uout[g3][4] = *(const float4*)&g_uout[g3 * 256 + c + 4];
    }

    float o[8];
    #pragma unroll
    for (int j = 0; j < 4; j++) {
        float2 sr = __half22float2(pr[j]);
        float2 si = __half22float2(pi[j]);
        float2 nn = __half22float2(pn[j]);
        float2 hh = __half22float2(ph[j]);
        float2 xx = __half22float2(px[j]);
        sr.x += s2.x * uin[0][j * 2] + s2.y * uout[0][j * 2];
        sr.y += s2.x * uin[0][j * 2 + 1] + s2.y * uout[0][j * 2 + 1];
        si.x += s2.x * uin[1][j * 2] + s2.y * uout[1][j * 2];
        si.y += s2.x * uin[1][j * 2 + 1] + s2.y * uout[1][j * 2 + 1];
        nn.x += s2.x * uin[2][j * 2] + s2.y * uout[2][j * 2];
        nn.y += s2.x * uin[2][j * 2 + 1] + s2.y * uout[2][j * 2 + 1];
        float rg0 = 1.f / (1.f + expf(-sr.x)), rg1 = 1.f / (1.f + expf(-sr.y));
        float ig0 = 1.f / (1.f + expf(-si.x)), ig1 = 1.f / (1.f + expf(-si.y));
        float ng0 = tanhf(nn.x + rg0 * hh.x), ng1 = tanhf(nn.y + rg1 * hh.y);
        o[j * 2 + 0] = ng0 + ig0 * (xx.x - ng0);
        o[j * 2 + 1] = ng1 + ig1 * (xx.y - ng1);
    }
    float* dst = out + (size_t)r * H_ + c;
    *(float4*)dst = *(float4*)&o[0];
    *(float4*)(dst + 4) = *(float4*)&o[4];
}

// ---------------- launcher ----------------
extern "C" void kernel_launch(void* const* d_in, const int* in_sizes, int n_in,
                              void* d_out, int out_size)
{
    const int*   inputs = (const int*)  d_in[0];   // [512,64]
    const float* Aadj   = (const float*)d_in[1];   // [512,64,128]
    const float* emb    = (const float*)d_in[2];   // [100000,256]
    const float* W_in   = (const float*)d_in[3];
    const float* b_in   = (const float*)d_in[4];
    const float* W_out  = (const float*)d_in[5];
    const float* b_out  = (const float*)d_in[6];
    const float* w_ih   = (const float*)d_in[7];   // [768,512]
    const float* b_ih   = (const float*)d_in[8];
    const float* w_hh   = (const float*)d_in[9];   // [768,256]
    const float* b_hh   = (const float*)d_in[10];
    const float* b_iah  = (const float*)d_in[11];
    const float* b_oah  = (const float*)d_in[12];
    float* out = (float*)d_out;

    static cudaStream_t s1 = nullptr;
    static cudaEvent_t evRoot = nullptr, evB = nullptr;
    static int init_done = 0;
    if (!init_done) {
        cudaStreamCreateWithFlags(&s1, cudaStreamNonBlocking);
        cudaEventCreateWithFlags(&evRoot, cudaEventDisableTiming);
        cudaEventCreateWithFlags(&evB, cudaEventDisableTiming);
        cudaFuncSetAttribute(wpack_gemm,
                             cudaFuncAttributeMaxDynamicSharedMemorySize, GM_SMEM);
        cudaFuncSetAttribute(gemm2,
                             cudaFuncAttributeMaxDynamicSharedMemorySize, GM_SMEM);
        init_done = 1;
    }

    // fork: branch B (activations) on s1, branch A (weights) on default
    cudaEventRecord(evRoot, 0);
    cudaStreamWaitEvent(s1, evRoot, 0);

    // branch A: weights path
    build_pack_fold<<<512, 256>>>(w_ih, w_hh, W_in, W_out,
                                  b_ih, b_hh, b_in, b_out, b_iah, b_oah);
    wpack_gemm<<<dim3(6, 4), 256, GM_SMEM>>>();

    // branch B: activations path
    gather_norm<<<BN_ / 8, 256, 0, s1>>>(inputs, emb);
    adjacency_mma<<<B_, 256, 0, s1>>>(Aadj);

    // join
    cudaEventRecord(evB, s1);
    cudaStreamWaitEvent(0, evB, 0);

    // GEMM2 (grouped K) -> g_G
    gemm2<<<dim3(BN_ / 128, NG / 128), 256, GM_SMEM>>>();

    // gates (+ rank-1 s·u terms)
    gates_kernel<<<(BN_ * 32 + 255) / 256, 256>>>(out);
}

// round 14
// speedup vs baseline: 1.1223x; 1.1223x over previous
#include <cuda_runtime.h>
#include <cuda_fp16.h>
#include <math.h>
#include <stdint.h>

// Problem constants
#define B_    512
#define N_    64
#define H_    256
#define BN_   32768          // B_*N_
#define KX    768            // X = [P_in(256) | P_out(256) | h(256)]
#define NG    1024           // G columns: [r-sum | i-sum | i_n | h_n]

// ---------------- device scratch (static, allocation-free) ----------------
__device__ __half g_X[(size_t)BN_ * KX];        // fp16 activations [32768,768]
__device__ __half g_G[(size_t)BN_ * NG];        // fp16 [32768,1024]
__device__ __half g_Wpack[NG * KX];             // packed weight [1024,768] fp16
__device__ __half g_wih16[768 * 512];           // w_ih fp16
__device__ __half g_WinT[256 * 256];            // W_in^T fp16
__device__ __half g_WoutT[256 * 256];           // W_out^T fp16
__device__ float  g_uin[NG];                    // w_ih1 @ b_in
__device__ float  g_uout[NG];                   // w_ih2 @ b_out
__device__ float  g_v[NG];                      // folded constant bias
__device__ float  g_S[BN_ * 2];                 // rowsums [s_in, s_out]
__device__ float  g_zero[256];

// ---------------- K0: pack weights + fold biases (merged) ----------
__global__ void build_pack_fold(
    const float* __restrict__ w_ih, const float* __restrict__ w_hh,
    const float* __restrict__ W_in, const float* __restrict__ W_out,
    const float* __restrict__ b_ih, const float* __restrict__ b_hh,
    const float* __restrict__ b_in, const float* __restrict__ b_out,
    const float* __restrict__ b_iah, const float* __restrict__ b_oah)
{
    const int stride = gridDim.x * blockDim.x;
    const int idx = blockIdx.x * blockDim.x + threadIdx.x;

    for (int i = idx; i < 768 * 512; i += stride)
        g_wih16[i] = __float2half_rn(w_ih[i]);
    for (int i = idx; i < 256 * 256; i += stride) {
        int k = i >> 8, j = i & 255;
        g_WinT[i]  = __float2half_rn(W_in[j * 256 + k]);
        g_WoutT[i] = __float2half_rn(W_out[j * 256 + k]);
    }
    // Wpack h-columns (512..768)
    for (int i = idx; i < NG * 256; i += stride) {
        int n = i >> 8, k = i & 255;
        float v;
        if (n < 512)      v = w_hh[n * 256 + k];
        else if (n < 768) v = 0.f;
        else              v = w_hh[(n - 256) * 256 + k];
        g_Wpack[(size_t)n * KX + 512 + k] = __float2half_rn(v);
    }
    for (int i = idx; i < 256; i += stride) g_zero[i] = 0.f;

    // fold biases: blocks 0..127 handle 8 n's each (warp per n)
    if (blockIdx.x < 128) {
        const int n = blockIdx.x * 8 + (threadIdx.x >> 5);
        const int lane = threadIdx.x & 31;
        if (n < 768) {
            const float* wr = w_ih + (size_t)n * 512;
            float d1 = 0.f, d2 = 0.f, d3 = 0.f, d4 = 0.f;
            #pragma unroll
            for (int j = lane; j < 256; j += 32) {
                float a = wr[j], c = wr[256 + j];
                d1 += a * b_in[j];
                d3 += a * b_iah[j];
                d2 += c * b_out[j];
                d4 += c * b_oah[j];
            }
            #pragma unroll
            for (int o = 16; o > 0; o >>= 1) {
                d1 += __shfl_xor_sync(0xffffffffu, d1, o);
                d2 += __shfl_xor_sync(0xffffffffu, d2, o);
                d3 += __shfl_xor_sync(0xffffffffu, d3, o);
                d4 += __shfl_xor_sync(0xffffffffu, d4, o);
            }
            if (lane == 0) {
                g_uin[n] = d1;
                g_uout[n] = d2;
                g_v[n] = d3 + d4 + b_ih[n] + (n < 512 ? b_hh[n] : 0.f);
            }
        } else if (lane == 0) {
            g_uin[n] = 0.f;
            g_uout[n] = 0.f;
            g_v[n] = b_hh[n - 256];
        }
    }
}

// ---------------- K1: gather + L2 normalize (warp per row) ----------
__global__ void __launch_bounds__(256) gather_norm(const int* __restrict__ inputs,
                                                   const float* __restrict__ emb)
{
    const int row = blockIdx.x * 8 + (threadIdx.x >> 5);
    const int lane = threadIdx.x & 31;
    const float4* e = (const float4*)(emb + (size_t)inputs[row] * H_) + lane * 2;
    float4 v0 = e[0], v1 = e[1];
    float ss = v0.x * v0.x + v0.y * v0.y + v0.z * v0.z + v0.w * v0.w
             + v1.x * v1.x + v1.y * v1.y + v1.z * v1.z + v1.w * v1.w;
    #pragma unroll
    for (int o = 16; o > 0; o >>= 1) ss += __shfl_xor_sync(0xffffffffu, ss, o);
    float sc = 1.f / (sqrtf(ss) + 1e-12f);
    __half2 h[4];
    h[0] = __floats2half2_rn(v0.x * sc, v0.y * sc);
    h[1] = __floats2half2_rn(v0.z * sc, v0.w * sc);
    h[2] = __floats2half2_rn(v1.x * sc, v1.y * sc);
    h[3] = __floats2half2_rn(v1.z * sc, v1.w * sc);
    *(uint4*)&g_X[(size_t)row * KX + 512 + lane * 8] = *(uint4*)h;
}

// ---------------- helpers ----------------
__device__ __forceinline__ void cp_async16(void* smem_dst, const void* gmem_src) {
    uint32_t sa = (uint32_t)__cvta_generic_to_shared(smem_dst);
    asm volatile("cp.async.cg.shared.global [%0], [%1], 16;\n" :: "r"(sa), "l"(gmem_src));
}
__device__ __forceinline__ void cp_commit() { asm volatile("cp.async.commit_group;\n"); }

__device__ __forceinline__ void ldm_x4(uint32_t& r0, uint32_t& r1, uint32_t& r2, uint32_t& r3,
                                       uint32_t addr) {
    asm volatile("ldmatrix.sync.aligned.m8n8.x4.shared.b16 {%0,%1,%2,%3}, [%4];"
                 : "=r"(r0), "=r"(r1), "=r"(r2), "=r"(r3) : "r"(addr));
}
__device__ __forceinline__ void ldm_x4_t(uint32_t& r0, uint32_t& r1, uint32_t& r2, uint32_t& r3,
                                         uint32_t addr) {
    asm volatile("ldmatrix.sync.aligned.m8n8.x4.trans.shared.b16 {%0,%1,%2,%3}, [%4];"
                 : "=r"(r0), "=r"(r1), "=r"(r2), "=r"(r3) : "r"(addr));
}
#define HMMA16816(ac, a0, a1, a2, a3, b0, b1)                                          \
    asm volatile(                                                                      \
        "mma.sync.aligned.m16n8k16.row.col.f32.f16.f16.f32 "                           \
        "{%0,%1,%2,%3}, {%4,%5,%6,%7}, {%8,%9}, {%0,%1,%2,%3};\n"                      \
        : "+f"((ac)[0]), "+f"((ac)[1]), "+f"((ac)[2]), "+f"((ac)[3])                   \
        : "r"(a0), "r"(a1), "r"(a2), "r"(a3), "r"(b0), "r"(b1))

// ---------------- GEMM body: 4-stage BK=32 pipeline (proven fastest) -------
#define ST_STRIDE 20                     // u32 per smem row (80 B, 16B aligned)
#define ST_TILE_U32 (128 * ST_STRIDE)    // 2560 u32 per tile
#define ST_STAGE_U32 (2 * ST_TILE_U32)   // 5120 u32 per stage
#define GM_SMEM (4 * ST_STAGE_U32 * 4)   // 81920 bytes

__device__ __forceinline__ void gemm_body(
    const __half* __restrict__ gA, int lda,
    const __half* __restrict__ gB, int ldb,
    const float* __restrict__ biasB,
    __half* __restrict__ Cb, int ldc,
    int kb, int ke)
{
    extern __shared__ uint32_t sm[];
    const uint32_t smBase = (uint32_t)__cvta_generic_to_shared(sm);

    const int tid = threadIdx.x;
    const int lane = tid & 31;
    const int g = lane >> 2;
    const int t = lane & 3;
    const int warpId = tid >> 5;
    const int wm = (warpId >> 2) * 64;
    const int wn = (warpId & 3) * 32;
    const int T = (ke - kb) >> 5;

    const int ldRow0 = tid >> 2;
    const int ldCol0 = (tid & 3);
    const int ldRow1 = (tid + 256) >> 2;
    const int ldCol1 = (tid + 256) & 3;

    const uint32_t aOff = (uint32_t)(((wm + (lane & 15)) * ST_STRIDE + (lane >> 4) * 4) * 4);
    const uint32_t bOff = (uint32_t)(((wn + (lane >> 4) * 8 + (lane & 7)) * ST_STRIDE
                                      + ((lane >> 3) & 1) * 4) * 4);

    float acc[4][4][4];
    #pragma unroll
    for (int i = 0; i < 4; i++)
        #pragma unroll
        for (int j = 0; j < 4; j++)
            #pragma unroll
            for (int c = 0; c < 4; c++) acc[i][j][c] = 0.f;

    auto load_stage = [&](int slot, int k0) {
        uint32_t* As = sm + slot * ST_STAGE_U32;
        uint32_t* Bs = As + ST_TILE_U32;
        cp_async16(As + ldRow0 * ST_STRIDE + ldCol0 * 4,
                   gA + (size_t)ldRow0 * lda + k0 + ldCol0 * 8);
        cp_async16(As + ldRow1 * ST_STRIDE + ldCol1 * 4,
                   gA + (size_t)ldRow1 * lda + k0 + ldCol1 * 8);
        cp_async16(Bs + ldRow0 * ST_STRIDE + ldCol0 * 4,
                   gB + (size_t)ldRow0 * ldb + k0 + ldCol0 * 8);
        cp_async16(Bs + ldRow1 * ST_STRIDE + ldCol1 * 4,
                   gB + (size_t)ldRow1 * ldb + k0 + ldCol1 * 8);
        cp_commit();
    };

    load_stage(0, kb);
    load_stage(1, kb + 32);
    load_stage(2, kb + 64);

    for (int kt = 0; kt < T; kt++) {
        if (kt <= T - 3)      asm volatile("cp.async.wait_group 2;\n" ::: "memory");
        else if (kt == T - 2) asm volatile("cp.async.wait_group 1;\n" ::: "memory");
        else                  asm volatile("cp.async.wait_group 0;\n" ::: "memory");
        __syncthreads();

        if (kt + 3 < T)
            load_stage((kt + 3) & 3, kb + (kt + 3) * 32);

        const uint32_t As_b = smBase + (uint32_t)((kt & 3) * ST_STAGE_U32 * 4);
        const uint32_t Bs_b = As_b + ST_TILE_U32 * 4;

        #pragma unroll
        for (int kk = 0; kk < 2; kk++) {
            uint32_t a[4][4];
            #pragma unroll
            for (int mt = 0; mt < 4; mt++)
                ldm_x4(a[mt][0], a[mt][1], a[mt][2], a[mt][3],
                       As_b + aOff + mt * (16 * ST_STRIDE * 4) + kk * 32);
            uint32_t b[4][2];
            ldm_x4(b[0][0], b[0][1], b[1][0], b[1][1], Bs_b + bOff + kk * 32);
            ldm_x4(b[2][0], b[2][1], b[3][0], b[3][1],
                   Bs_b + bOff + 2 * (8 * ST_STRIDE * 4) + kk * 32);

            #pragma unroll
            for (int mt = 0; mt < 4; mt++)
                #pragma unroll
                for (int nt = 0; nt < 4; nt++)
                    HMMA16816(acc[mt][nt], a[mt][0], a[mt][1], a[mt][2], a[mt][3],
                              b[nt][0], b[nt][1]);
        }
    }

    #pragma unroll
    for (int nt = 0; nt < 4; nt++) {
        const int col = wn + nt * 8 + t * 2;
        const float b0 = biasB[col], b1 = biasB[col + 1];
        #pragma unroll
        for (int mt = 0; mt < 4; mt++) {
            const int row = wm + mt * 16 + g;
            *(__half2*)(Cb + (size_t)row * ldc + col) =
                __floats2half2_rn(acc[mt][nt][0] + b0, acc[mt][nt][1] + b1);
            *(__half2*)(Cb + (size_t)(row + 8) * ldc + col) =
                __floats2half2_rn(acc[mt][nt][2] + b0, acc[mt][nt][3] + b1);
        }
    }
}

// ---------------- K2: merged Wpack M-GEMMs (one launch) ----------
__global__ void __launch_bounds__(256, 2) wpack_gemm()
{
    const int m0 = blockIdx.x * 128;
    const int sel = blockIdx.y >> 1;
    const int n0 = (blockIdx.y & 1) * 128;
    const __half* gA = g_wih16 + (size_t)m0 * 512 + sel * 256;
    const __half* gB = (sel ? g_WoutT : g_WinT) + (size_t)n0 * 256;
    __half* Cb = g_Wpack + (size_t)m0 * KX + sel * 256 + n0;
    gemm_body(gA, 512, gB, 256, g_zero, Cb, KX, 0, 256);
}

// ---------------- K4: GEMM2 (grouped K) -> g_G ----------------
__global__ void __launch_bounds__(256, 2) gemm2()
{
    const int m0 = blockIdx.x * 128;
    const int n0 = blockIdx.y * 128;
    int kb, ke;
    if (n0 >= 768)      { kb = 512; ke = 768; }
    else if (n0 >= 512) { kb = 0;   ke = 512; }
    else                { kb = 0;   ke = 768; }
    gemm_body(g_X + (size_t)m0 * KX, KX,
              g_Wpack + (size_t)n0 * KX, KX,
              g_v + n0,
              g_G + (size_t)m0 * NG + n0, NG, kb, ke);
}

// ---------------- K3: adjacency, one CTA per batch ----------------
// A (64x128, both halves) loaded once; h loaded in 2 chunks of 128 cols;
// per chunk: both halves computed with short-lived acc[2][4][4].
#define SA2_STRIDE 68     // u32 per A row (128 halves + 4 pad), 272 B
#define SHC_STRIDE 68     // u32 per h-chunk row (128 halves + 4 pad)
__global__ void __launch_bounds__(256) adjacency_mma(const float* __restrict__ Aadj)
{
    __shared__ __align__(16) uint32_t shA[64 * SA2_STRIDE];   // 17408 B
    __shared__ __align__(16) uint32_t shH[64 * SHC_STRIDE];   // 17408 B
    const int b = blockIdx.x;
    const int tid = threadIdx.x;
    const int lane = tid & 31;
    const int wid = tid >> 5;
    const int mw = wid >> 2;           // 0..1 (32 rows)
    const int nw = wid & 3;            // 0..3 (32 cols within 128-chunk)
    const int g = lane >> 2;
    const int t = lane & 3;
    const float* Ab = Aadj + (size_t)b * (64 * 128);
    const int r0 = b * 64;

    const uint32_t shA_b = (uint32_t)__cvta_generic_to_shared(shA);
    const uint32_t shH_b = (uint32_t)__cvta_generic_to_shared(shH);

    // load full A (64x128 fp32 -> fp16), both halves, once
    for (int i = tid; i < 64 * 64; i += 256) {
        int n = i >> 6, m2 = (i & 63) * 2;
        float2 v = *(const float2*)&Ab[n * 128 + m2];
        *(__half2*)&shA[n * SA2_STRIDE + m2 / 2] = __floats2half2_rn(v.x, v.y);
    }
    // rowsums for both halves (threads 0..127)
    if (tid < 128) {
        const int half = tid >> 6, n = tid & 63;
        const float* ar = Ab + n * 128 + half * 64;
        float s = 0.f;
        #pragma unroll 8
        for (int m = 0; m < 64; m++) s += ar[m];
        g_S[(size_t)(r0 + n) * 2 + half] = s;
    }

    const uint32_t aOffE = (uint32_t)(((mw * 32 + (lane & 15)) * SA2_STRIDE
                                       + (lane >> 4) * 4) * 4);
    const uint32_t hOffE = (uint32_t)(((lane & 15) * SHC_STRIDE + nw * 16
                                       + (lane >> 4) * 4) * 4);

    for (int chunk = 0; chunk < 2; chunk++) {
        __syncthreads();   // protect shH overwrite (and shA stores on first iter)
        // load h chunk (64 rows x 128 halves)
        for (int i = tid; i < 64 * 16; i += 256) {
            int m = i >> 4, c8 = (i & 15) * 8;
            uint4 v = *(const uint4*)&g_X[(size_t)(r0 + m) * KX + 512
                                          + chunk * 128 + c8];
            *(uint4*)&shH[m * SHC_STRIDE + c8 / 2] = v;
        }
        __syncthreads();

        #pragma unroll 1
        for (int half = 0; half < 2; half++) {
            float acc[2][4][4];
            #pragma unroll
            for (int i = 0; i < 2; i++)
                #pragma unroll
                for (int j = 0; j < 4; j++)
                    #pragma unroll
                    for (int c = 0; c < 4; c++) acc[i][j][c] = 0.f;

            #pragma unroll
            for (int kk = 0; kk < 4; kk++) {
                uint32_t a[2][4];
                #pragma unroll
                for (int mt = 0; mt < 2; mt++)
                    ldm_x4(a[mt][0], a[mt][1], a[mt][2], a[mt][3],
                           shA_b + aOffE + mt * (16 * SA2_STRIDE * 4)
                           + half * 128 + kk * 32);
                uint32_t bb[4][2];
                ldm_x4_t(bb[0][0], bb[0][1], bb[1][0], bb[1][1],
                         shH_b + hOffE + kk * (16 * SHC_STRIDE * 4));
                ldm_x4_t(bb[2][0], bb[2][1], bb[3][0], bb[3][1],
                         shH_b + hOffE + kk * (16 * SHC_STRIDE * 4) + 32);
                #pragma unroll
                for (int mt = 0; mt < 2; mt++)
                    #pragma unroll
                    for (int nt = 0; nt < 4; nt++)
                        HMMA16816(acc[mt][nt], a[mt][0], a[mt][1], a[mt][2], a[mt][3],
                                  bb[nt][0], bb[nt][1]);
            }

            #pragma unroll
            for (int nt = 0; nt < 4; nt++) {
                const int c = nw * 32 + nt * 8 + t * 2;
                const int cc = half * 256 + chunk * 128 + c;
                #pragma unroll
                for (int mt = 0; mt < 2; mt++) {
                    const int n = mw * 32 + mt * 16 + g;
                    *(__half2*)&g_X[(size_t)(r0 + n) * KX + cc] =
                        __floats2half2_rn(acc[mt][nt][0], acc[mt][nt][1]);
                    *(__half2*)&g_X[(size_t)(r0 + n + 8) * KX + cc] =
                        __floats2half2_rn(acc[mt][nt][2], acc[mt][nt][3]);
                }
            }
        }
    }
}

// ---------------- K5: gates epilogue -> out ----------------
__global__ void __launch_bounds__(256) gates_kernel(float* __restrict__ out)
{
    int idx = blockIdx.x * blockDim.x + threadIdx.x;
    if (idx >= BN_ * 32) return;
    int r = idx >> 5;
    int c = (idx & 31) << 3;
    const __half* Gr = g_G + (size_t)r * NG;
    uint4 vr = *(const uint4*)&Gr[c];
    uint4 vi = *(const uint4*)&Gr[256 + c];
    uint4 vn = *(const uint4*)&Gr[512 + c];
    uint4 vh = *(const uint4*)&Gr[768 + c];
    uint4 vx = *(const uint4*)&g_X[(size_t)r * KX + 512 + c];
    const __half2* pr = (const __half2*)&vr;
    const __half2* pi = (const __half2*)&vi;
    const __half2* pn = (const __half2*)&vn;
    const __half2* ph = (const __half2*)&vh;
    const __half2* px = (const __half2*)&vx;

    float2 s2 = *(const float2*)&g_S[(size_t)r * 2];
    float uin[3][8], uout[3][8];
    #pragma unroll
    for (int g3 = 0; g3 < 3; g3++) {
        *(float4*)&uin[g3][0]  = *(const float4*)&g_uin[g3 * 256 + c];
        *(float4*)&uin[g3][4]  = *(const float4*)&g_uin[g3 * 256 + c + 4];
        *(float4*)&uout[g3][0] = *(const float4*)&g_uout[g3 * 256 + c];
        *(float4*)&uout[g3][4] = *(const float4*)&g_uout[g3 * 256 + c + 4];
    }

    float o[8];
    #pragma unroll
    for (int j = 0; j < 4; j++) {
        float2 sr = __half22float2(pr[j]);
        float2 si = __half22float2(pi[j]);
        float2 nn = __half22float2(pn[j]);
        float2 hh = __half22float2(ph[j]);
        float2 xx = __half22float2(px[j]);
        sr.x += s2.x * uin[0][j * 2] + s2.y * uout[0][j * 2];
        sr.y += s2.x * uin[0][j * 2 + 1] + s2.y * uout[0][j * 2 + 1];
        si.x += s2.x * uin[1][j * 2] + s2.y * uout[1][j * 2];
        si.y += s2.x * uin[1][j * 2 + 1] + s2.y * uout[1][j * 2 + 1];
        nn.x += s2.x * uin[2][j * 2] + s2.y * uout[2][j * 2];
        nn.y += s2.x * uin[2][j * 2 + 1] + s2.y * uout[2][j * 2 + 1];
        float rg0 = 1.f / (1.f + expf(-sr.x)), rg1 = 1.f / (1.f + expf(-sr.y));
        float ig0 = 1.f / (1.f + expf(-si.x)), ig1 = 1.f / (1.f + expf(-si.y));
        float ng0 = tanhf(nn.x + rg0 * hh.x), ng1 = tanhf(nn.y + rg1 * hh.y);
        o[j * 2 + 0] = ng0 + ig0 * (xx.x - ng0);
        o[j * 2 + 1] = ng1 + ig1 * (xx.y - ng1);
    }
    float* dst = out + (size_t)r * H_ + c;
    *(float4*)dst = *(float4*)&o[0];
    *(float4*)(dst + 4) = *(float4*)&o[4];
}

// ---------------- launcher ----------------
extern "C" void kernel_launch(void* const* d_in, const int* in_sizes, int n_in,
                              void* d_out, int out_size)
{
    const int*   inputs = (const int*)  d_in[0];   // [512,64]
    const float* Aadj   = (const float*)d_in[1];   // [512,64,128]
    const float* emb    = (const float*)d_in[2];   // [100000,256]
    const float* W_in   = (const float*)d_in[3];
    const float* b_in   = (const float*)d_in[4];
    const float* W_out  = (const float*)d_in[5];
    const float* b_out  = (const float*)d_in[6];
    const float* w_ih   = (const float*)d_in[7];   // [768,512]
    const float* b_ih   = (const float*)d_in[8];
    const float* w_hh   = (const float*)d_in[9];   // [768,256]
    const float* b_hh   = (const float*)d_in[10];
    const float* b_iah  = (const float*)d_in[11];
    const float* b_oah  = (const float*)d_in[12];
    float* out = (float*)d_out;

    static cudaStream_t s1 = nullptr;
    static cudaEvent_t evRoot = nullptr, evB = nullptr;
    static int init_done = 0;
    if (!init_done) {
        cudaStreamCreateWithFlags(&s1, cudaStreamNonBlocking);
        cudaEventCreateWithFlags(&evRoot, cudaEventDisableTiming);
        cudaEventCreateWithFlags(&evB, cudaEventDisableTiming);
        cudaFuncSetAttribute(wpack_gemm,
                             cudaFuncAttributeMaxDynamicSharedMemorySize, GM_SMEM);
        cudaFuncSetAttribute(gemm2,
                             cudaFuncAttributeMaxDynamicSharedMemorySize, GM_SMEM);
        init_done = 1;
    }

    // fork: branch B (activations) on s1, branch A (weights) on default
    cudaEventRecord(evRoot, 0);
    cudaStreamWaitEvent(s1, evRoot, 0);

    // branch A: weights path
    build_pack_fold<<<512, 256>>>(w_ih, w_hh, W_in, W_out,
                                  b_ih, b_hh, b_in, b_out, b_iah, b_oah);
    wpack_gemm<<<dim3(6, 4), 256, GM_SMEM>>>();

    // branch B: activations path
    gather_norm<<<BN_ / 8, 256, 0, s1>>>(inputs, emb);
    adjacency_mma<<<B_, 256, 0, s1>>>(Aadj);

    // join
    cudaEventRecord(evB, s1);
    cudaStreamWaitEvent(0, evB, 0);

    // GEMM2 (grouped K) -> g_G
    gemm2<<<dim3(BN_ / 128, NG / 128), 256, GM_SMEM>>>();

    // gates (+ rank-1 s·u terms)
    gates_kernel<<<(BN_ * 32 + 255) / 256, 256>>>(out);
}

// round 15
// speedup vs baseline: 1.1806x; 1.0520x over previous
#include <cuda_runtime.h>
#include <cuda_fp16.h>
#include <math.h>
#include <stdint.h>

// Problem constants
#define B_    512
#define N_    64
#define H_    256
#define BN_   32768          // B_*N_
#define KX    768            // X = [P_in(256) | P_out(256) | h(256)]
#define NG    1024           // G columns: [r-sum | i-sum | i_n | h_n]

// ---------------- device scratch (static, allocation-free) ----------------
__device__ __half g_X[(size_t)BN_ * KX];
__device__ __half g_G[(size_t)BN_ * NG];
__device__ __half g_Wpack[NG * KX];
__device__ __half g_wih16[768 * 512];
__device__ __half g_WinT[256 * 256];
__device__ __half g_WoutT[256 * 256];
__device__ float  g_uin[NG];
__device__ float  g_uout[NG];
__device__ float  g_v[NG];
__device__ float  g_S[BN_ * 2];
__device__ float  g_zero[256];

// ---------------- K0: pack weights + fold biases (merged) ----------
__global__ void build_pack_fold(
    const float* __restrict__ w_ih, const float* __restrict__ w_hh,
    const float* __restrict__ W_in, const float* __restrict__ W_out,
    const float* __restrict__ b_ih, const float* __restrict__ b_hh,
    const float* __restrict__ b_in, const float* __restrict__ b_out,
    const float* __restrict__ b_iah, const float* __restrict__ b_oah)
{
    const int stride = gridDim.x * blockDim.x;
    const int idx = blockIdx.x * blockDim.x + threadIdx.x;

    for (int i = idx; i < 768 * 512; i += stride)
        g_wih16[i] = __float2half_rn(w_ih[i]);
    for (int i = idx; i < 256 * 256; i += stride) {
        int k = i >> 8, j = i & 255;
        g_WinT[i]  = __float2half_rn(W_in[j * 256 + k]);
        g_WoutT[i] = __float2half_rn(W_out[j * 256 + k]);
    }
    for (int i = idx; i < NG * 256; i += stride) {
        int n = i >> 8, k = i & 255;
        float v;
        if (n < 512)      v = w_hh[n * 256 + k];
        else if (n < 768) v = 0.f;
        else              v = w_hh[(n - 256) * 256 + k];
        g_Wpack[(size_t)n * KX + 512 + k] = __float2half_rn(v);
    }
    for (int i = idx; i < 256; i += stride) g_zero[i] = 0.f;

    if (blockIdx.x < 128) {
        const int n = blockIdx.x * 8 + (threadIdx.x >> 5);
        const int lane = threadIdx.x & 31;
        if (n < 768) {
            const float* wr = w_ih + (size_t)n * 512;
            float d1 = 0.f, d2 = 0.f, d3 = 0.f, d4 = 0.f;
            #pragma unroll
            for (int j = lane; j < 256; j += 32) {
                float a = wr[j], c = wr[256 + j];
                d1 += a * b_in[j];
                d3 += a * b_iah[j];
                d2 += c * b_out[j];
                d4 += c * b_oah[j];
            }
            #pragma unroll
            for (int o = 16; o > 0; o >>= 1) {
                d1 += __shfl_xor_sync(0xffffffffu, d1, o);
                d2 += __shfl_xor_sync(0xffffffffu, d2, o);
                d3 += __shfl_xor_sync(0xffffffffu, d3, o);
                d4 += __shfl_xor_sync(0xffffffffu, d4, o);
            }
            if (lane == 0) {
                g_uin[n] = d1;
                g_uout[n] = d2;
                g_v[n] = d3 + d4 + b_ih[n] + (n < 512 ? b_hh[n] : 0.f);
            }
        } else if (lane == 0) {
            g_uin[n] = 0.f;
            g_uout[n] = 0.f;
            g_v[n] = b_hh[n - 256];
        }
    }
}

// ---------------- K1: gather + L2 normalize (warp per row) ----------
__global__ void __launch_bounds__(256) gather_norm(const int* __restrict__ inputs,
                                                   const float* __restrict__ emb)
{
    const int row = blockIdx.x * 8 + (threadIdx.x >> 5);
    const int lane = threadIdx.x & 31;
    const float4* e = (const float4*)(emb + (size_t)inputs[row] * H_) + lane * 2;
    float4 v0 = e[0], v1 = e[1];
    float ss = v0.x * v0.x + v0.y * v0.y + v0.z * v0.z + v0.w * v0.w
             + v1.x * v1.x + v1.y * v1.y + v1.z * v1.z + v1.w * v1.w;
    #pragma unroll
    for (int o = 16; o > 0; o >>= 1) ss += __shfl_xor_sync(0xffffffffu, ss, o);
    float sc = 1.f / (sqrtf(ss) + 1e-12f);
    __half2 h[4];
    h[0] = __floats2half2_rn(v0.x * sc, v0.y * sc);
    h[1] = __floats2half2_rn(v0.z * sc, v0.w * sc);
    h[2] = __floats2half2_rn(v1.x * sc, v1.y * sc);
    h[3] = __floats2half2_rn(v1.z * sc, v1.w * sc);
    *(uint4*)&g_X[(size_t)row * KX + 512 + lane * 8] = *(uint4*)h;
}

// ---------------- helpers ----------------
__device__ __forceinline__ void cp_async16(void* smem_dst, const void* gmem_src) {
    uint32_t sa = (uint32_t)__cvta_generic_to_shared(smem_dst);
    asm volatile("cp.async.cg.shared.global [%0], [%1], 16;\n" :: "r"(sa), "l"(gmem_src));
}
__device__ __forceinline__ void cp_commit() { asm volatile("cp.async.commit_group;\n"); }

__device__ __forceinline__ void ldm_x4(uint32_t& r0, uint32_t& r1, uint32_t& r2, uint32_t& r3,
                                       uint32_t addr) {
    asm volatile("ldmatrix.sync.aligned.m8n8.x4.shared.b16 {%0,%1,%2,%3}, [%4];"
                 : "=r"(r0), "=r"(r1), "=r"(r2), "=r"(r3) : "r"(addr));
}
__device__ __forceinline__ void ldm_x4_t(uint32_t& r0, uint32_t& r1, uint32_t& r2, uint32_t& r3,
                                         uint32_t addr) {
    asm volatile("ldmatrix.sync.aligned.m8n8.x4.trans.shared.b16 {%0,%1,%2,%3}, [%4];"
                 : "=r"(r0), "=r"(r1), "=r"(r2), "=r"(r3) : "r"(addr));
}
#define HMMA16816(ac, a0, a1, a2, a3, b0, b1)                                          \
    asm volatile(                                                                      \
        "mma.sync.aligned.m16n8k16.row.col.f32.f16.f16.f32 "                           \
        "{%0,%1,%2,%3}, {%4,%5,%6,%7}, {%8,%9}, {%0,%1,%2,%3};\n"                      \
        : "+f"((ac)[0]), "+f"((ac)[1]), "+f"((ac)[2]), "+f"((ac)[3])                   \
        : "r"(a0), "r"(a1), "r"(a2), "r"(a3), "r"(b0), "r"(b1))

// ---------------- GEMM body: 4-stage BK=32 pipeline ----------------
#define ST_STRIDE 20
#define ST_TILE_U32 (128 * ST_STRIDE)
#define ST_STAGE_U32 (2 * ST_TILE_U32)
#define GM_SMEM (4 * ST_STAGE_U32 * 4)   // 81920 bytes

__device__ __forceinline__ void gemm_body(
    const __half* __restrict__ gA, int lda,
    const __half* __restrict__ gB, int ldb,
    const float* __restrict__ biasB,
    __half* __restrict__ Cb, int ldc,
    int kb, int ke)
{
    extern __shared__ uint32_t sm[];
    const uint32_t smBase = (uint32_t)__cvta_generic_to_shared(sm);

    const int tid = threadIdx.x;
    const int lane = tid & 31;
    const int g = lane >> 2;
    const int t = lane & 3;
    const int warpId = tid >> 5;
    const int wm = (warpId >> 2) * 64;
    const int wn = (warpId & 3) * 32;
    const int T = (ke - kb) >> 5;

    const int ldRow0 = tid >> 2;
    const int ldCol0 = (tid & 3);
    const int ldRow1 = (tid + 256) >> 2;
    const int ldCol1 = (tid + 256) & 3;

    const uint32_t aOff = (uint32_t)(((wm + (lane & 15)) * ST_STRIDE + (lane >> 4) * 4) * 4);
    const uint32_t bOff = (uint32_t)(((wn + (lane >> 4) * 8 + (lane & 7)) * ST_STRIDE
                                      + ((lane >> 3) & 1) * 4) * 4);

    float acc[4][4][4];
    #pragma unroll
    for (int i = 0; i < 4; i++)
        #pragma unroll
        for (int j = 0; j < 4; j++)
            #pragma unroll
            for (int c = 0; c < 4; c++) acc[i][j][c] = 0.f;

    auto load_stage = [&](int slot, int k0) {
        uint32_t* As = sm + slot * ST_STAGE_U32;
        uint32_t* Bs = As + ST_TILE_U32;
        cp_async16(As + ldRow0 * ST_STRIDE + ldCol0 * 4,
                   gA + (size_t)ldRow0 * lda + k0 + ldCol0 * 8);
        cp_async16(As + ldRow1 * ST_STRIDE + ldCol1 * 4,
                   gA + (size_t)ldRow1 * lda + k0 + ldCol1 * 8);
        cp_async16(Bs + ldRow0 * ST_STRIDE + ldCol0 * 4,
                   gB + (size_t)ldRow0 * ldb + k0 + ldCol0 * 8);
        cp_async16(Bs + ldRow1 * ST_STRIDE + ldCol1 * 4,
                   gB + (size_t)ldRow1 * ldb + k0 + ldCol1 * 8);
        cp_commit();
    };

    load_stage(0, kb);
    load_stage(1, kb + 32);
    load_stage(2, kb + 64);

    for (int kt = 0; kt < T; kt++) {
        if (kt <= T - 3)      asm volatile("cp.async.wait_group 2;\n" ::: "memory");
        else if (kt == T - 2) asm volatile("cp.async.wait_group 1;\n" ::: "memory");
        else                  asm volatile("cp.async.wait_group 0;\n" ::: "memory");
        __syncthreads();

        if (kt + 3 < T)
            load_stage((kt + 3) & 3, kb + (kt + 3) * 32);

        const uint32_t As_b = smBase + (uint32_t)((kt & 3) * ST_STAGE_U32 * 4);
        const uint32_t Bs_b = As_b + ST_TILE_U32 * 4;

        #pragma unroll
        for (int kk = 0; kk < 2; kk++) {
            uint32_t a[4][4];
            #pragma unroll
            for (int mt = 0; mt < 4; mt++)
                ldm_x4(a[mt][0], a[mt][1], a[mt][2], a[mt][3],
                       As_b + aOff + mt * (16 * ST_STRIDE * 4) + kk * 32);
            uint32_t b[4][2];
            ldm_x4(b[0][0], b[0][1], b[1][0], b[1][1], Bs_b + bOff + kk * 32);
            ldm_x4(b[2][0], b[2][1], b[3][0], b[3][1],
                   Bs_b + bOff + 2 * (8 * ST_STRIDE * 4) + kk * 32);

            #pragma unroll
            for (int mt = 0; mt < 4; mt++)
                #pragma unroll
                for (int nt = 0; nt < 4; nt++)
                    HMMA16816(acc[mt][nt], a[mt][0], a[mt][1], a[mt][2], a[mt][3],
                              b[nt][0], b[nt][1]);
        }
    }

    #pragma unroll
    for (int nt = 0; nt < 4; nt++) {
        const int col = wn + nt * 8 + t * 2;
        const float b0 = biasB[col], b1 = biasB[col + 1];
        #pragma unroll
        for (int mt = 0; mt < 4; mt++) {
            const int row = wm + mt * 16 + g;
            *(__half2*)(Cb + (size_t)row * ldc + col) =
                __floats2half2_rn(acc[mt][nt][0] + b0, acc[mt][nt][1] + b1);
            *(__half2*)(Cb + (size_t)(row + 8) * ldc + col) =
                __floats2half2_rn(acc[mt][nt][2] + b0, acc[mt][nt][3] + b1);
        }
    }
}

// ---------------- K2: merged Wpack M-GEMMs ----------
__global__ void __launch_bounds__(256, 2) wpack_gemm()
{
    const int m0 = blockIdx.x * 128;
    const int sel = blockIdx.y >> 1;
    const int n0 = (blockIdx.y & 1) * 128;
    const __half* gA = g_wih16 + (size_t)m0 * 512 + sel * 256;
    const __half* gB = (sel ? g_WoutT : g_WinT) + (size_t)n0 * 256;
    __half* Cb = g_Wpack + (size_t)m0 * KX + sel * 256 + n0;
    gemm_body(gA, 512, gB, 256, g_zero, Cb, KX, 0, 256);
}

// ---------------- K4a: GEMM2 h_n blocks (n0 >= 768, K 512..768) ------------
// Depends only on build_pack_fold (w_hh static region) + gather_norm (h).
__global__ void __launch_bounds__(256, 2) gemm2_hn()
{
    const int m0 = blockIdx.x * 128;
    const int n0 = 768 + blockIdx.y * 128;
    gemm_body(g_X + (size_t)m0 * KX, KX,
              g_Wpack + (size_t)n0 * KX, KX,
              g_v + n0,
              g_G + (size_t)m0 * NG + n0, NG, 512, 768);
}

// ---------------- K4b: GEMM2 remaining blocks (n0 < 768) ----------
__global__ void __launch_bounds__(256, 2) gemm2_main()
{
    const int m0 = blockIdx.x * 128;
    const int n0 = blockIdx.y * 128;
    int kb = 0, ke = (n0 >= 512) ? 512 : 768;   // i_n: K 0..512; r/i: 0..768
    gemm_body(g_X + (size_t)m0 * KX, KX,
              g_Wpack + (size_t)n0 * KX, KX,
              g_v + n0,
              g_G + (size_t)m0 * NG + n0, NG, kb, ke);
}

// ---------------- K3: adjacency, cp.async pipelined ----------------
#define SA2_STRIDE 68     // u32 per A row (128 halves + 4 pad)
#define SHC_STRIDE 68     // u32 per h-chunk row (128 halves + 4 pad)
__global__ void __launch_bounds__(256) adjacency_mma(const float* __restrict__ Aadj)
{
    __shared__ __align__(16) uint32_t shA[64 * SA2_STRIDE];        // 17408 B
    __shared__ __align__(16) uint32_t shH[2][64 * SHC_STRIDE];     // 34816 B
    const int b = blockIdx.x;
    const int tid = threadIdx.x;
    const int lane = tid & 31;
    const int wid = tid >> 5;
    const int mw = wid >> 2;
    const int nw = wid & 3;
    const int g = lane >> 2;
    const int t = lane & 3;
    const float* Ab = Aadj + (size_t)b * (64 * 128);
    const int r0 = b * 64;

    const uint32_t shA_b = (uint32_t)__cvta_generic_to_shared(shA);

    // cp.async h chunk 0 (64 rows x 128 halves = 1024 x 16B chunks)
    #pragma unroll
    for (int j = 0; j < 4; j++) {
        int i = tid + j * 256;
        int m = i >> 4, c4 = (i & 15) * 4;     // u32 col within row
        cp_async16(&shH[0][m * SHC_STRIDE + c4],
                   &g_X[(size_t)(r0 + m) * KX + 512 + c4 * 2]);
    }
    cp_commit();

    // A load (fp32) -> convert -> STS (overlaps with cp.async above)
    #pragma unroll
    for (int j = 0; j < 16; j++) {
        int i = tid + j * 256;
        int n = i >> 6, m2 = (i & 63) * 2;
        float2 v = *(const float2*)&Ab[n * 128 + m2];
        *(__half2*)&shA[n * SA2_STRIDE + m2 / 2] = __floats2half2_rn(v.x, v.y);
    }

    // cp.async h chunk 1
    #pragma unroll
    for (int j = 0; j < 4; j++) {
        int i = tid + j * 256;
        int m = i >> 4, c4 = (i & 15) * 4;
        cp_async16(&shH[1][m * SHC_STRIDE + c4],
                   &g_X[(size_t)(r0 + m) * KX + 512 + 128 + c4 * 2]);
    }
    cp_commit();

    // rowsums (global reads hit L1 — lines just fetched by A load)
    if (tid < 128) {
        const int half = tid >> 6, n = tid & 63;
        const float* ar = Ab + n * 128 + half * 64;
        float s = 0.f;
        #pragma unroll 8
        for (int m = 0; m < 64; m++) s += ar[m];
        g_S[(size_t)(r0 + n) * 2 + half] = s;
    }

    const uint32_t aOffE = (uint32_t)(((mw * 32 + (lane & 15)) * SA2_STRIDE
                                       + (lane >> 4) * 4) * 4);
    const uint32_t hOffL = (uint32_t)(((lane & 15) * SHC_STRIDE + nw * 16
                                       + (lane >> 4) * 4) * 4);

    #pragma unroll 1
    for (int chunk = 0; chunk < 2; chunk++) {
        if (chunk == 0) asm volatile("cp.async.wait_group 1;\n" ::: "memory");
        else            asm volatile("cp.async.wait_group 0;\n" ::: "memory");
        __syncthreads();

        const uint32_t shH_b = (uint32_t)__cvta_generic_to_shared(&shH[chunk][0]);

        #pragma unroll 1
        for (int half = 0; half < 2; half++) {
            float acc[2][4][4];
            #pragma unroll
            for (int i = 0; i < 2; i++)
                #pragma unroll
                for (int j = 0; j < 4; j++)
                    #pragma unroll
                    for (int c = 0; c < 4; c++) acc[i][j][c] = 0.f;

            #pragma unroll
            for (int kk = 0; kk < 4; kk++) {
                uint32_t a[2][4];
                #pragma unroll
                for (int mt = 0; mt < 2; mt++)
                    ldm_x4(a[mt][0], a[mt][1], a[mt][2], a[mt][3],
                           shA_b + aOffE + mt * (16 * SA2_STRIDE * 4)
                           + half * 128 + kk * 32);
                uint32_t bb[4][2];
                ldm_x4_t(bb[0][0], bb[0][1], bb[1][0], bb[1][1],
                         shH_b + hOffL + kk * (16 * SHC_STRIDE * 4));
                ldm_x4_t(bb[2][0], bb[2][1], bb[3][0], bb[3][1],
                         shH_b + hOffL + kk * (16 * SHC_STRIDE * 4) + 32);
                #pragma unroll
                for (int mt = 0; mt < 2; mt++)
                    #pragma unroll
                    for (int nt = 0; nt < 4; nt++)
                        HMMA16816(acc[mt][nt], a[mt][0], a[mt][1], a[mt][2], a[mt][3],
                                  bb[nt][0], bb[nt][1]);
            }

            #pragma unroll
            for (int nt = 0; nt < 4; nt++) {
                const int c = nw * 32 + nt * 8 + t * 2;
                const int cc = half * 256 + chunk * 128 + c;
                #pragma unroll
                for (int mt = 0; mt < 2; mt++) {
                    const int n = mw * 32 + mt * 16 + g;
                    *(__half2*)&g_X[(size_t)(r0 + n) * KX + cc] =
                        __floats2half2_rn(acc[mt][nt][0], acc[mt][nt][1]);
                    *(__half2*)&g_X[(size_t)(r0 + n + 8) * KX + cc] =
                        __floats2half2_rn(acc[mt][nt][2], acc[mt][nt][3]);
                }
            }
        }
    }
}

// ---------------- K5: gates epilogue -> out ----------------
__global__ void __launch_bounds__(256) gates_kernel(float* __restrict__ out)
{
    int idx = blockIdx.x * blockDim.x + threadIdx.x;
    if (idx >= BN_ * 32) return;
    int r = idx >> 5;
    int c = (idx & 31) << 3;
    const __half* Gr = g_G + (size_t)r * NG;
    uint4 vr = *(const uint4*)&Gr[c];
    uint4 vi = *(const uint4*)&Gr[256 + c];
    uint4 vn = *(const uint4*)&Gr[512 + c];
    uint4 vh = *(const uint4*)&Gr[768 + c];
    uint4 vx = *(const uint4*)&g_X[(size_t)r * KX + 512 + c];
    const __half2* pr = (const __half2*)&vr;
    const __half2* pi = (const __half2*)&vi;
    const __half2* pn = (const __half2*)&vn;
    const __half2* ph = (const __half2*)&vh;
    const __half2* px = (const __half2*)&vx;

    float2 s2 = *(const float2*)&g_S[(size_t)r * 2];
    float uin[3][8], uout[3][8];
    #pragma unroll
    for (int g3 = 0; g3 < 3; g3++) {
        *(float4*)&uin[g3][0]  = *(const float4*)&g_uin[g3 * 256 + c];
        *(float4*)&uin[g3][4]  = *(const float4*)&g_uin[g3 * 256 + c + 4];
        *(float4*)&uout[g3][0] = *(const float4*)&g_uout[g3 * 256 + c];
        *(float4*)&uout[g3][4] = *(const float4*)&g_uout[g3 * 256 + c + 4];
    }

    float o[8];
    #pragma unroll
    for (int j = 0; j < 4; j++) {
        float2 sr = __half22float2(pr[j]);
        float2 si = __half22float2(pi[j]);
        float2 nn = __half22float2(pn[j]);
        float2 hh = __half22float2(ph[j]);
        float2 xx = __half22float2(px[j]);
        sr.x += s2.x * uin[0][j * 2] + s2.y * uout[0][j * 2];
        sr.y += s2.x * uin[0][j * 2 + 1] + s2.y * uout[0][j * 2 + 1];
        si.x += s2.x * uin[1][j * 2] + s2.y * uout[1][j * 2];
        si.y += s2.x * uin[1][j * 2 + 1] + s2.y * uout[1][j * 2 + 1];
        nn.x += s2.x * uin[2][j * 2] + s2.y * uout[2][j * 2];
        nn.y += s2.x * uin[2][j * 2 + 1] + s2.y * uout[2][j * 2 + 1];
        float rg0 = 1.f / (1.f + expf(-sr.x)), rg1 = 1.f / (1.f + expf(-sr.y));
        float ig0 = 1.f / (1.f + expf(-si.x)), ig1 = 1.f / (1.f + expf(-si.y));
        float ng0 = tanhf(nn.x + rg0 * hh.x), ng1 = tanhf(nn.y + rg1 * hh.y);
        o[j * 2 + 0] = ng0 + ig0 * (xx.x - ng0);
        o[j * 2 + 1] = ng1 + ig1 * (xx.y - ng1);
    }
    float* dst = out + (size_t)r * H_ + c;
    *(float4*)dst = *(float4*)&o[0];
    *(float4*)(dst + 4) = *(float4*)&o[4];
}

// ---------------- launcher ----------------
extern "C" void kernel_launch(void* const* d_in, const int* in_sizes, int n_in,
                              void* d_out, int out_size)
{
    const int*   inputs = (const int*)  d_in[0];
    const float* Aadj   = (const float*)d_in[1];
    const float* emb    = (const float*)d_in[2];
    const float* W_in   = (const float*)d_in[3];
    const float* b_in   = (const float*)d_in[4];
    const float* W_out  = (const float*)d_in[5];
    const float* b_out  = (const float*)d_in[6];
    const float* w_ih   = (const float*)d_in[7];
    const float* b_ih   = (const float*)d_in[8];
    const float* w_hh   = (const float*)d_in[9];
    const float* b_hh   = (const float*)d_in[10];
    const float* b_iah  = (const float*)d_in[11];
    const float* b_oah  = (const float*)d_in[12];
    float* out = (float*)d_out;

    static cudaStream_t s1 = nullptr;
    static cudaEvent_t evRoot = nullptr, evG = nullptr, evB = nullptr;
    static int init_done = 0;
    if (!init_done) {
        cudaStreamCreateWithFlags(&s1, cudaStreamNonBlocking);
        cudaEventCreateWithFlags(&evRoot, cudaEventDisableTiming);
        cudaEventCreateWithFlags(&evG, cudaEventDisableTiming);
        cudaEventCreateWithFlags(&evB, cudaEventDisableTiming);
        cudaFuncSetAttribute(wpack_gemm,
                             cudaFuncAttributeMaxDynamicSharedMemorySize, GM_SMEM);
        cudaFuncSetAttribute(gemm2_hn,
                             cudaFuncAttributeMaxDynamicSharedMemorySize, GM_SMEM);
        cudaFuncSetAttribute(gemm2_main,
                             cudaFuncAttributeMaxDynamicSharedMemorySize, GM_SMEM);
        init_done = 1;
    }

    // fork
    cudaEventRecord(evRoot, 0);
    cudaStreamWaitEvent(s1, evRoot, 0);

    // branch A (weights, default stream)
    build_pack_fold<<<512, 256>>>(w_ih, w_hh, W_in, W_out,
                                  b_ih, b_hh, b_in, b_out, b_iah, b_oah);
    wpack_gemm<<<dim3(6, 4), 256, GM_SMEM>>>();

    // branch B (activations, s1)
    gather_norm<<<BN_ / 8, 256, 0, s1>>>(inputs, emb);
    cudaEventRecord(evG, s1);
    adjacency_mma<<<B_, 256, 0, s1>>>(Aadj);
    cudaEventRecord(evB, s1);

    // gemm2 h_n blocks: need build_pack_fold (default) + gather_norm (evG);
    // runs concurrently with adjacency_mma.
    cudaStreamWaitEvent(0, evG, 0);
    gemm2_hn<<<dim3(BN_ / 128, 2), 256, GM_SMEM>>>();

    // join: remaining gemm2 blocks need adjacency output
    cudaStreamWaitEvent(0, evB, 0);
    gemm2_main<<<dim3(BN_ / 128, 6), 256, GM_SMEM>>>();

    // gates
    gates_kernel<<<(BN_ * 32 + 255) / 256, 256>>>(out);
}

// round 16
// speedup vs baseline: 1.1917x; 1.0094x over previous
#include <cuda_runtime.h>
#include <cuda_fp16.h>
#include <math.h>
#include <stdint.h>

// Problem constants
#define B_    512
#define N_    64
#define H_    256
#define BN_   32768          // B_*N_
#define KX    768            // X = [P_in(256) | P_out(256) | h(256)]
#define NG    1024           // G columns: [r-sum | i-sum | i_n | h_n]

// ---------------- device scratch (static, allocation-free) ----------------
__device__ __half g_X[(size_t)BN_ * KX];
__device__ __half g_G[(size_t)BN_ * NG];
__device__ __half g_Wpack[NG * KX];
__device__ __half g_wih16[768 * 512];
__device__ __half g_WinT[256 * 256];
__device__ __half g_WoutT[256 * 256];
__device__ float  g_uin[NG];
__device__ float  g_uout[NG];
__device__ float  g_v[NG];
__device__ float  g_S[BN_ * 2];
__device__ float  g_zero[256];

// ---------------- K0: pack weights + fold biases (merged) ----------
__global__ void build_pack_fold(
    const float* __restrict__ w_ih, const float* __restrict__ w_hh,
    const float* __restrict__ W_in, const float* __restrict__ W_out,
    const float* __restrict__ b_ih, const float* __restrict__ b_hh,
    const float* __restrict__ b_in, const float* __restrict__ b_out,
    const float* __restrict__ b_iah, const float* __restrict__ b_oah)
{
    const int stride = gridDim.x * blockDim.x;
    const int idx = blockIdx.x * blockDim.x + threadIdx.x;

    for (int i = idx; i < 768 * 512; i += stride)
        g_wih16[i] = __float2half_rn(w_ih[i]);
    for (int i = idx; i < 256 * 256; i += stride) {
        int k = i >> 8, j = i & 255;
        g_WinT[i]  = __float2half_rn(W_in[j * 256 + k]);
        g_WoutT[i] = __float2half_rn(W_out[j * 256 + k]);
    }
    for (int i = idx; i < NG * 256; i += stride) {
        int n = i >> 8, k = i & 255;
        float v;
        if (n < 512)      v = w_hh[n * 256 + k];
        else if (n < 768) v = 0.f;
        else              v = w_hh[(n - 256) * 256 + k];
        g_Wpack[(size_t)n * KX + 512 + k] = __float2half_rn(v);
    }
    for (int i = idx; i < 256; i += stride) g_zero[i] = 0.f;

    if (blockIdx.x < 128) {
        const int n = blockIdx.x * 8 + (threadIdx.x >> 5);
        const int lane = threadIdx.x & 31;
        if (n < 768) {
            const float* wr = w_ih + (size_t)n * 512;
            float d1 = 0.f, d2 = 0.f, d3 = 0.f, d4 = 0.f;
            #pragma unroll
            for (int j = lane; j < 256; j += 32) {
                float a = wr[j], c = wr[256 + j];
                d1 += a * b_in[j];
                d3 += a * b_iah[j];
                d2 += c * b_out[j];
                d4 += c * b_oah[j];
            }
            #pragma unroll
            for (int o = 16; o > 0; o >>= 1) {
                d1 += __shfl_xor_sync(0xffffffffu, d1, o);
                d2 += __shfl_xor_sync(0xffffffffu, d2, o);
                d3 += __shfl_xor_sync(0xffffffffu, d3, o);
                d4 += __shfl_xor_sync(0xffffffffu, d4, o);
            }
            if (lane == 0) {
                g_uin[n] = d1;
                g_uout[n] = d2;
                g_v[n] = d3 + d4 + b_ih[n] + (n < 512 ? b_hh[n] : 0.f);
            }
        } else if (lane == 0) {
            g_uin[n] = 0.f;
            g_uout[n] = 0.f;
            g_v[n] = b_hh[n - 256];
        }
    }
}

// ---------------- K1: gather + L2 normalize (warp per row, M-split) --------
__global__ void __launch_bounds__(256) gather_norm(const int* __restrict__ inputs,
                                                   const float* __restrict__ emb,
                                                   int rowOff)
{
    const int row = rowOff + blockIdx.x * 8 + (threadIdx.x >> 5);
    const int lane = threadIdx.x & 31;
    const float4* e = (const float4*)(emb + (size_t)inputs[row] * H_) + lane * 2;
    float4 v0 = e[0], v1 = e[1];
    float ss = v0.x * v0.x + v0.y * v0.y + v0.z * v0.z + v0.w * v0.w
             + v1.x * v1.x + v1.y * v1.y + v1.z * v1.z + v1.w * v1.w;
    #pragma unroll
    for (int o = 16; o > 0; o >>= 1) ss += __shfl_xor_sync(0xffffffffu, ss, o);
    float sc = 1.f / (sqrtf(ss) + 1e-12f);
    __half2 h[4];
    h[0] = __floats2half2_rn(v0.x * sc, v0.y * sc);
    h[1] = __floats2half2_rn(v0.z * sc, v0.w * sc);
    h[2] = __floats2half2_rn(v1.x * sc, v1.y * sc);
    h[3] = __floats2half2_rn(v1.z * sc, v1.w * sc);
    *(uint4*)&g_X[(size_t)row * KX + 512 + lane * 8] = *(uint4*)h;
}

// ---------------- helpers ----------------
__device__ __forceinline__ void cp_async16(void* smem_dst, const void* gmem_src) {
    uint32_t sa = (uint32_t)__cvta_generic_to_shared(smem_dst);
    asm volatile("cp.async.cg.shared.global [%0], [%1], 16;\n" :: "r"(sa), "l"(gmem_src));
}
__device__ __forceinline__ void cp_commit() { asm volatile("cp.async.commit_group;\n"); }

__device__ __forceinline__ void ldm_x4(uint32_t& r0, uint32_t& r1, uint32_t& r2, uint32_t& r3,
                                       uint32_t addr) {
    asm volatile("ldmatrix.sync.aligned.m8n8.x4.shared.b16 {%0,%1,%2,%3}, [%4];"
                 : "=r"(r0), "=r"(r1), "=r"(r2), "=r"(r3) : "r"(addr));
}
__device__ __forceinline__ void ldm_x4_t(uint32_t& r0, uint32_t& r1, uint32_t& r2, uint32_t& r3,
                                         uint32_t addr) {
    asm volatile("ldmatrix.sync.aligned.m8n8.x4.trans.shared.b16 {%0,%1,%2,%3}, [%4];"
                 : "=r"(r0), "=r"(r1), "=r"(r2), "=r"(r3) : "r"(addr));
}
#define HMMA16816(ac, a0, a1, a2, a3, b0, b1)                                          \
    asm volatile(                                                                      \
        "mma.sync.aligned.m16n8k16.row.col.f32.f16.f16.f32 "                           \
        "{%0,%1,%2,%3}, {%4,%5,%6,%7}, {%8,%9}, {%0,%1,%2,%3};\n"                      \
        : "+f"((ac)[0]), "+f"((ac)[1]), "+f"((ac)[2]), "+f"((ac)[3])                   \
        : "r"(a0), "r"(a1), "r"(a2), "r"(a3), "r"(b0), "r"(b1))

// ---------------- GEMM body: 4-stage BK=32 pipeline ----------------
#define ST_STRIDE 20
#define ST_TILE_U32 (128 * ST_STRIDE)
#define ST_STAGE_U32 (2 * ST_TILE_U32)
#define GM_SMEM (4 * ST_STAGE_U32 * 4)   // 81920 bytes

__device__ __forceinline__ void gemm_body(
    const __half* __restrict__ gA, int lda,
    const __half* __restrict__ gB, int ldb,
    const float* __restrict__ biasB,
    __half* __restrict__ Cb, int ldc,
    int kb, int ke)
{
    extern __shared__ uint32_t sm[];
    const uint32_t smBase = (uint32_t)__cvta_generic_to_shared(sm);

    const int tid = threadIdx.x;
    const int lane = tid & 31;
    const int g = lane >> 2;
    const int t = lane & 3;
    const int warpId = tid >> 5;
    const int wm = (warpId >> 2) * 64;
    const int wn = (warpId & 3) * 32;
    const int T = (ke - kb) >> 5;

    const int ldRow0 = tid >> 2;
    const int ldCol0 = (tid & 3);
    const int ldRow1 = (tid + 256) >> 2;
    const int ldCol1 = (tid + 256) & 3;

    const uint32_t aOff = (uint32_t)(((wm + (lane & 15)) * ST_STRIDE + (lane >> 4) * 4) * 4);
    const uint32_t bOff = (uint32_t)(((wn + (lane >> 4) * 8 + (lane & 7)) * ST_STRIDE
                                      + ((lane >> 3) & 1) * 4) * 4);

    float acc[4][4][4];
    #pragma unroll
    for (int i = 0; i < 4; i++)
        #pragma unroll
        for (int j = 0; j < 4; j++)
            #pragma unroll
            for (int c = 0; c < 4; c++) acc[i][j][c] = 0.f;

    auto load_stage = [&](int slot, int k0) {
        uint32_t* As = sm + slot * ST_STAGE_U32;
        uint32_t* Bs = As + ST_TILE_U32;
        cp_async16(As + ldRow0 * ST_STRIDE + ldCol0 * 4,
                   gA + (size_t)ldRow0 * lda + k0 + ldCol0 * 8);
        cp_async16(As + ldRow1 * ST_STRIDE + ldCol1 * 4,
                   gA + (size_t)ldRow1 * lda + k0 + ldCol1 * 8);
        cp_async16(Bs + ldRow0 * ST_STRIDE + ldCol0 * 4,
                   gB + (size_t)ldRow0 * ldb + k0 + ldCol0 * 8);
        cp_async16(Bs + ldRow1 * ST_STRIDE + ldCol1 * 4,
                   gB + (size_t)ldRow1 * ldb + k0 + ldCol1 * 8);
        cp_commit();
    };

    load_stage(0, kb);
    load_stage(1, kb + 32);
    load_stage(2, kb + 64);

    for (int kt = 0; kt < T; kt++) {
        if (kt <= T - 3)      asm volatile("cp.async.wait_group 2;\n" ::: "memory");
        else if (kt == T - 2) asm volatile("cp.async.wait_group 1;\n" ::: "memory");
        else                  asm volatile("cp.async.wait_group 0;\n" ::: "memory");
        __syncthreads();

        if (kt + 3 < T)
            load_stage((kt + 3) & 3, kb + (kt + 3) * 32);

        const uint32_t As_b = smBase + (uint32_t)((kt & 3) * ST_STAGE_U32 * 4);
        const uint32_t Bs_b = As_b + ST_TILE_U32 * 4;

        #pragma unroll
        for (int kk = 0; kk < 2; kk++) {
            uint32_t a[4][4];
            #pragma unroll
            for (int mt = 0; mt < 4; mt++)
                ldm_x4(a[mt][0], a[mt][1], a[mt][2], a[mt][3],
                       As_b + aOff + mt * (16 * ST_STRIDE * 4) + kk * 32);
            uint32_t b[4][2];
            ldm_x4(b[0][0], b[0][1], b[1][0], b[1][1], Bs_b + bOff + kk * 32);
            ldm_x4(b[2][0], b[2][1], b[3][0], b[3][1],
                   Bs_b + bOff + 2 * (8 * ST_STRIDE * 4) + kk * 32);

            #pragma unroll
            for (int mt = 0; mt < 4; mt++)
                #pragma unroll
                for (int nt = 0; nt < 4; nt++)
                    HMMA16816(acc[mt][nt], a[mt][0], a[mt][1], a[mt][2], a[mt][3],
                              b[nt][0], b[nt][1]);
        }
    }

    #pragma unroll
    for (int nt = 0; nt < 4; nt++) {
        const int col = wn + nt * 8 + t * 2;
        const float b0 = biasB[col], b1 = biasB[col + 1];
        #pragma unroll
        for (int mt = 0; mt < 4; mt++) {
            const int row = wm + mt * 16 + g;
            *(__half2*)(Cb + (size_t)row * ldc + col) =
                __floats2half2_rn(acc[mt][nt][0] + b0, acc[mt][nt][1] + b1);
            *(__half2*)(Cb + (size_t)(row + 8) * ldc + col) =
                __floats2half2_rn(acc[mt][nt][2] + b0, acc[mt][nt][3] + b1);
        }
    }
}

// ---------------- K2: merged Wpack M-GEMMs ----------
__global__ void __launch_bounds__(256, 2) wpack_gemm()
{
    const int m0 = blockIdx.x * 128;
    const int sel = blockIdx.y >> 1;
    const int n0 = (blockIdx.y & 1) * 128;
    const __half* gA = g_wih16 + (size_t)m0 * 512 + sel * 256;
    const __half* gB = (sel ? g_WoutT : g_WinT) + (size_t)n0 * 256;
    __half* Cb = g_Wpack + (size_t)m0 * KX + sel * 256 + n0;
    gemm_body(gA, 512, gB, 256, g_zero, Cb, KX, 0, 256);
}

// ---------------- K4a: GEMM2 h_n blocks (n0 >= 768, K 512..768) ------------
__global__ void __launch_bounds__(256, 2) gemm2_hn()
{
    const int m0 = blockIdx.x * 128;
    const int n0 = 768 + blockIdx.y * 128;
    gemm_body(g_X + (size_t)m0 * KX, KX,
              g_Wpack + (size_t)n0 * KX, KX,
              g_v + n0,
              g_G + (size_t)m0 * NG + n0, NG, 512, 768);
}

// ---------------- K4b: GEMM2 remaining blocks (n0 < 768), M-split ----------
__global__ void __launch_bounds__(256, 2) gemm2_main(int mBlkOff)
{
    const int m0 = (mBlkOff + blockIdx.x) * 128;
    const int n0 = blockIdx.y * 128;
    int kb = 0, ke = (n0 >= 512) ? 512 : 768;
    gemm_body(g_X + (size_t)m0 * KX, KX,
              g_Wpack + (size_t)n0 * KX, KX,
              g_v + n0,
              g_G + (size_t)m0 * NG + n0, NG, kb, ke);
}

// ---------------- K3: adjacency, cp.async pipelined, batch-split -----------
#define SA2_STRIDE 68
#define SHC_STRIDE 68
__global__ void __launch_bounds__(256) adjacency_mma(const float* __restrict__ Aadj,
                                                     int batchOff)
{
    __shared__ __align__(16) uint32_t shA[64 * SA2_STRIDE];
    __shared__ __align__(16) uint32_t shH[2][64 * SHC_STRIDE];
    const int b = batchOff + blockIdx.x;
    const int tid = threadIdx.x;
    const int lane = tid & 31;
    const int wid = tid >> 5;
    const int mw = wid >> 2;
    const int nw = wid & 3;
    const int g = lane >> 2;
    const int t = lane & 3;
    const float* Ab = Aadj + (size_t)b * (64 * 128);
    const int r0 = b * 64;

    const uint32_t shA_b = (uint32_t)__cvta_generic_to_shared(shA);

    #pragma unroll
    for (int j = 0; j < 4; j++) {
        int i = tid + j * 256;
        int m = i >> 4, c4 = (i & 15) * 4;
        cp_async16(&shH[0][m * SHC_STRIDE + c4],
                   &g_X[(size_t)(r0 + m) * KX + 512 + c4 * 2]);
    }
    cp_commit();

    #pragma unroll
    for (int j = 0; j < 16; j++) {
        int i = tid + j * 256;
        int n = i >> 6, m2 = (i & 63) * 2;
        float2 v = *(const float2*)&Ab[n * 128 + m2];
        *(__half2*)&shA[n * SA2_STRIDE + m2 / 2] = __floats2half2_rn(v.x, v.y);
    }

    #pragma unroll
    for (int j = 0; j < 4; j++) {
        int i = tid + j * 256;
        int m = i >> 4, c4 = (i & 15) * 4;
        cp_async16(&shH[1][m * SHC_STRIDE + c4],
                   &g_X[(size_t)(r0 + m) * KX + 512 + 128 + c4 * 2]);
    }
    cp_commit();

    if (tid < 128) {
        const int half = tid >> 6, n = tid & 63;
        const float* ar = Ab + n * 128 + half * 64;
        float s = 0.f;
        #pragma unroll 8
        for (int m = 0; m < 64; m++) s += ar[m];
        g_S[(size_t)(r0 + n) * 2 + half] = s;
    }

    const uint32_t aOffE = (uint32_t)(((mw * 32 + (lane & 15)) * SA2_STRIDE
                                       + (lane >> 4) * 4) * 4);
    const uint32_t hOffL = (uint32_t)(((lane & 15) * SHC_STRIDE + nw * 16
                                       + (lane >> 4) * 4) * 4);

    #pragma unroll 1
    for (int chunk = 0; chunk < 2; chunk++) {
        if (chunk == 0) asm volatile("cp.async.wait_group 1;\n" ::: "memory");
        else            asm volatile("cp.async.wait_group 0;\n" ::: "memory");
        __syncthreads();

        const uint32_t shH_b = (uint32_t)__cvta_generic_to_shared(&shH[chunk][0]);

        #pragma unroll 1
        for (int half = 0; half < 2; half++) {
            float acc[2][4][4];
            #pragma unroll
            for (int i = 0; i < 2; i++)
                #pragma unroll
                for (int j = 0; j < 4; j++)
                    #pragma unroll
                    for (int c = 0; c < 4; c++) acc[i][j][c] = 0.f;

            #pragma unroll
            for (int kk = 0; kk < 4; kk++) {
                uint32_t a[2][4];
                #pragma unroll
                for (int mt = 0; mt < 2; mt++)
                    ldm_x4(a[mt][0], a[mt][1], a[mt][2], a[mt][3],
                           shA_b + aOffE + mt * (16 * SA2_STRIDE * 4)
                           + half * 128 + kk * 32);
                uint32_t bb[4][2];
                ldm_x4_t(bb[0][0], bb[0][1], bb[1][0], bb[1][1],
                         shH_b + hOffL + kk * (16 * SHC_STRIDE * 4));
                ldm_x4_t(bb[2][0], bb[2][1], bb[3][0], bb[3][1],
                         shH_b + hOffL + kk * (16 * SHC_STRIDE * 4) + 32);
                #pragma unroll
                for (int mt = 0; mt < 2; mt++)
                    #pragma unroll
                    for (int nt = 0; nt < 4; nt++)
                        HMMA16816(acc[mt][nt], a[mt][0], a[mt][1], a[mt][2], a[mt][3],
                                  bb[nt][0], bb[nt][1]);
            }

            #pragma unroll
            for (int nt = 0; nt < 4; nt++) {
                const int c = nw * 32 + nt * 8 + t * 2;
                const int cc = half * 256 + chunk * 128 + c;
                #pragma unroll
                for (int mt = 0; mt < 2; mt++) {
                    const int n = mw * 32 + mt * 16 + g;
                    *(__half2*)&g_X[(size_t)(r0 + n) * KX + cc] =
                        __floats2half2_rn(acc[mt][nt][0], acc[mt][nt][1]);
                    *(__half2*)&g_X[(size_t)(r0 + n + 8) * KX + cc] =
                        __floats2half2_rn(acc[mt][nt][2], acc[mt][nt][3]);
                }
            }
        }
    }
}

// ---------------- K5: gates epilogue -> out (M-split) ----------------
__global__ void __launch_bounds__(256) gates_kernel(float* __restrict__ out, int rowOff)
{
    int idx = blockIdx.x * blockDim.x + threadIdx.x;   // over (BN_/2)*32
    int r = rowOff + (idx >> 5);
    int c = (idx & 31) << 3;
    const __half* Gr = g_G + (size_t)r * NG;
    uint4 vr = *(const uint4*)&Gr[c];
    uint4 vi = *(const uint4*)&Gr[256 + c];
    uint4 vn = *(const uint4*)&Gr[512 + c];
    uint4 vh = *(const uint4*)&Gr[768 + c];
    uint4 vx = *(const uint4*)&g_X[(size_t)r * KX + 512 + c];
    const __half2* pr = (const __half2*)&vr;
    const __half2* pi = (const __half2*)&vi;
    const __half2* pn = (const __half2*)&vn;
    const __half2* ph = (const __half2*)&vh;
    const __half2* px = (const __half2*)&vx;

    float2 s2 = *(const float2*)&g_S[(size_t)r * 2];
    float uin[3][8], uout[3][8];
    #pragma unroll
    for (int g3 = 0; g3 < 3; g3++) {
        *(float4*)&uin[g3][0]  = *(const float4*)&g_uin[g3 * 256 + c];
        *(float4*)&uin[g3][4]  = *(const float4*)&g_uin[g3 * 256 + c + 4];
        *(float4*)&uout[g3][0] = *(const float4*)&g_uout[g3 * 256 + c];
        *(float4*)&uout[g3][4] = *(const float4*)&g_uout[g3 * 256 + c + 4];
    }

    float o[8];
    #pragma unroll
    for (int j = 0; j < 4; j++) {
        float2 sr = __half22float2(pr[j]);
        float2 si = __half22float2(pi[j]);
        float2 nn = __half22float2(pn[j]);
        float2 hh = __half22float2(ph[j]);
        float2 xx = __half22float2(px[j]);
        sr.x += s2.x * uin[0][j * 2] + s2.y * uout[0][j * 2];
        sr.y += s2.x * uin[0][j * 2 + 1] + s2.y * uout[0][j * 2 + 1];
        si.x += s2.x * uin[1][j * 2] + s2.y * uout[1][j * 2];
        si.y += s2.x * uin[1][j * 2 + 1] + s2.y * uout[1][j * 2 + 1];
        nn.x += s2.x * uin[2][j * 2] + s2.y * uout[2][j * 2];
        nn.y += s2.x * uin[2][j * 2 + 1] + s2.y * uout[2][j * 2 + 1];
        float rg0 = 1.f / (1.f + expf(-sr.x)), rg1 = 1.f / (1.f + expf(-sr.y));
        float ig0 = 1.f / (1.f + expf(-si.x)), ig1 = 1.f / (1.f + expf(-si.y));
        float ng0 = tanhf(nn.x + rg0 * hh.x), ng1 = tanhf(nn.y + rg1 * hh.y);
        o[j * 2 + 0] = ng0 + ig0 * (xx.x - ng0);
        o[j * 2 + 1] = ng1 + ig1 * (xx.y - ng1);
    }
    float* dst = out + (size_t)r * H_ + c;
    *(float4*)dst = *(float4*)&o[0];
    *(float4*)(dst + 4) = *(float4*)&o[4];
}

// ---------------- launcher ----------------
extern "C" void kernel_launch(void* const* d_in, const int* in_sizes, int n_in,
                              void* d_out, int out_size)
{
    const int*   inputs = (const int*)  d_in[0];
    const float* Aadj   = (const float*)d_in[1];
    const float* emb    = (const float*)d_in[2];
    const float* W_in   = (const float*)d_in[3];
    const float* b_in   = (const float*)d_in[4];
    const float* W_out  = (const float*)d_in[5];
    const float* b_out  = (const float*)d_in[6];
    const float* w_ih   = (const float*)d_in[7];
    const float* b_ih   = (const float*)d_in[8];
    const float* w_hh   = (const float*)d_in[9];
    const float* b_hh   = (const float*)d_in[10];
    const float* b_iah  = (const float*)d_in[11];
    const float* b_oah  = (const float*)d_in[12];
    float* out = (float*)d_out;

    static cudaStream_t s1 = nullptr;
    static cudaEvent_t evRoot, evG1, evG2, evA1, evA2, evM1, evM2, evDone;
    static int init_done = 0;
    if (!init_done) {
        cudaStreamCreateWithFlags(&s1, cudaStreamNonBlocking);
        cudaEventCreateWithFlags(&evRoot, cudaEventDisableTiming);
        cudaEventCreateWithFlags(&evG1, cudaEventDisableTiming);
        cudaEventCreateWithFlags(&evG2, cudaEventDisableTiming);
        cudaEventCreateWithFlags(&evA1, cudaEventDisableTiming);
        cudaEventCreateWithFlags(&evA2, cudaEventDisableTiming);
        cudaEventCreateWithFlags(&evM1, cudaEventDisableTiming);
        cudaEventCreateWithFlags(&evM2, cudaEventDisableTiming);
        cudaEventCreateWithFlags(&evDone, cudaEventDisableTiming);
        cudaFuncSetAttribute(wpack_gemm,
                             cudaFuncAttributeMaxDynamicSharedMemorySize, GM_SMEM);
        cudaFuncSetAttribute(gemm2_hn,
                             cudaFuncAttributeMaxDynamicSharedMemorySize, GM_SMEM);
        cudaFuncSetAttribute(gemm2_main,
                             cudaFuncAttributeMaxDynamicSharedMemorySize, GM_SMEM);
        init_done = 1;
    }

    // fork
    cudaEventRecord(evRoot, 0);
    cudaStreamWaitEvent(s1, evRoot, 0);

    // branch A (weights, default stream)
    build_pack_fold<<<512, 256>>>(w_ih, w_hh, W_in, W_out,
                                  b_ih, b_hh, b_in, b_out, b_iah, b_oah);
    wpack_gemm<<<dim3(6, 4), 256, GM_SMEM>>>();

    // branch B (activations, s1), M-split pipeline
    gather_norm<<<2048, 256, 0, s1>>>(inputs, emb, 0);
    gather_norm<<<2048, 256, 0, s1>>>(inputs, emb, BN_ / 2);
    cudaEventRecord(evG2, s1);
    adjacency_mma<<<B_ / 2, 256, 0, s1>>>(Aadj, 0);
    cudaEventRecord(evA1, s1);
    adjacency_mma<<<B_ / 2, 256, 0, s1>>>(Aadj, B_ / 2);
    cudaEventRecord(evA2, s1);

    // gemm2 h_n blocks: need pack (s0 order) + all gather (evG2); overlaps adjacency
    cudaStreamWaitEvent(0, evG2, 0);
    gemm2_hn<<<dim3(BN_ / 128, 2), 256, GM_SMEM>>>();

    // gemm2_main first M half — overlaps adjacency second half
    cudaStreamWaitEvent(0, evA1, 0);
    gemm2_main<<<dim3(BN_ / 256, 6), 256, GM_SMEM>>>(0);
    cudaEventRecord(evM1, 0);

    // gemm2_main second M half
    cudaStreamWaitEvent(0, evA2, 0);
    gemm2_main<<<dim3(BN_ / 256, 6), 256, GM_SMEM>>>(BN_ / 256);
    cudaEventRecord(evM2, 0);

    // gates halves on s1 — first half overlaps gemm2_main second half
    cudaStreamWaitEvent(s1, evM1, 0);
    gates_kernel<<<2048, 256, 0, s1>>>(out, 0);
    cudaStreamWaitEvent(s1, evM2, 0);
    gates_kernel<<<2048, 256, 0, s1>>>(out, BN_ / 2);
    cudaEventRecord(evDone, s1);
    cudaStreamWaitEvent(0, evDone, 0);
}